// round 2
// baseline (speedup 1.0000x reference)
#include <cuda_runtime.h>
#include <math.h>

#define N   384
#define NN  (384*384)
#define HA  256

// ---- scratch (device globals; no allocation allowed) ----
__device__ float g_q   [HA*N];   // [o][n]  query = Wq @ nodes
__device__ float g_Kn  [HA*N];   // [o][n]  node part of key
__device__ float g_Vn  [HA*N];   // [o][n]  node part of value
__device__ float g_nf  [HA*N];   // [hv][n] node_features
__device__ float g_hEo [64*N];   // [o][n]  0.5 * (We[:, :256] @ nf)
__device__ float g_mask[N];      // decoded mask as float 0/1

// ============================================================
// Kernel 0: dtype-agnostic mask decode -> g_mask (float 0/1).
// Reads only first 384 bytes (valid for u8/int32/float32 layouts).
// ============================================================
__global__ __launch_bounds__(384) void k_mask(const unsigned int* __restrict__ m)
{
    __shared__ int mode;   // 0 = word-per-element (int32 or float32), 2 = packed u8
    int tid = threadIdx.x;
    if (tid == 0) {
        int md = 0;
        for (int w = 0; w < 96; w++) {
            unsigned v = m[w];
            if (v == 0x3f800000u) { md = 0; break; }   // float32 1.0 -> word mode
            if (v > 1u)          { md = 2; break; }    // upper bytes set -> packed u8
        }
        mode = md;
    }
    __syncthreads();
    float val;
    if (mode == 2) {
        unsigned w = m[tid >> 2];
        val = ((w >> ((tid & 3) * 8)) & 0xffu) ? 1.0f : 0.0f;
    } else {
        // works for both int32 (0/1) and float32 (0x0 / 0x3f800000)
        val = m[tid] ? 1.0f : 0.0f;
    }
    g_mask[tid] = val;
}

// ============================================================
// Kernel 1: fused GEMM, M=768 (q|Kn|Vn), K=128, Ncols=384
// grid (12,3), 256 threads. Tile 64 rows x 128 cols.
// ============================================================
__global__ __launch_bounds__(256) void k_prep(
    const float* __restrict__ nodes,
    const float* __restrict__ Wq,
    const float* __restrict__ Wk,
    const float* __restrict__ Wv)
{
    __shared__ float Ws[64][33];
    __shared__ float Ns[32][132];
    int tid = threadIdx.x;
    int r0 = blockIdx.x * 64, n0 = blockIdx.y * 128;
    int og = tid >> 4, jg = tid & 15;
    int ro = og * 4, co = jg * 8;

    float acc[4][8];
    #pragma unroll
    for (int q = 0; q < 4; q++)
        #pragma unroll
        for (int u = 0; u < 8; u++) acc[q][u] = 0.f;

    for (int k0 = 0; k0 < 128; k0 += 32) {
        {
            int rr = tid >> 2, kk0 = (tid & 3) * 8;
            int r = r0 + rr;
            const float* wp;
            if      (r < 256) wp = Wq + r * 128;
            else if (r < 512) wp = Wk + (r - 256) * 192;
            else              wp = Wv + (r - 512) * 192;
            float4 a = *(const float4*)(wp + k0 + kk0);
            float4 b = *(const float4*)(wp + k0 + kk0 + 4);
            Ws[rr][kk0+0]=a.x; Ws[rr][kk0+1]=a.y; Ws[rr][kk0+2]=a.z; Ws[rr][kk0+3]=a.w;
            Ws[rr][kk0+4]=b.x; Ws[rr][kk0+5]=b.y; Ws[rr][kk0+6]=b.z; Ws[rr][kk0+7]=b.w;
        }
        {
            int kk = tid >> 3, nn0 = (tid & 7) * 16;
            const float* np = nodes + (k0 + kk) * N + n0 + nn0;
            #pragma unroll
            for (int u = 0; u < 16; u += 4)
                *(float4*)&Ns[kk][nn0 + u] = *(const float4*)(np + u);
        }
        __syncthreads();
        #pragma unroll
        for (int kk = 0; kk < 32; kk++) {
            float w0 = Ws[ro+0][kk], w1 = Ws[ro+1][kk];
            float w2 = Ws[ro+2][kk], w3 = Ws[ro+3][kk];
            float4 nA = *(const float4*)&Ns[kk][co];
            float4 nB = *(const float4*)&Ns[kk][co+4];
            float nv[8] = {nA.x,nA.y,nA.z,nA.w,nB.x,nB.y,nB.z,nB.w};
            #pragma unroll
            for (int u = 0; u < 8; u++) {
                acc[0][u] = fmaf(w0, nv[u], acc[0][u]);
                acc[1][u] = fmaf(w1, nv[u], acc[1][u]);
                acc[2][u] = fmaf(w2, nv[u], acc[2][u]);
                acc[3][u] = fmaf(w3, nv[u], acc[3][u]);
            }
        }
        __syncthreads();
    }
    #pragma unroll
    for (int q = 0; q < 4; q++) {
        int r = r0 + ro + q;
        float* op;
        if      (r < 256) op = g_q  + r * N;
        else if (r < 512) op = g_Kn + (r - 256) * N;
        else              op = g_Vn + (r - 512) * N;
        #pragma unroll
        for (int u = 0; u < 8; u++) op[n0 + co + u] = acc[q][u];
    }
}

// ============================================================
// Kernel 2: fused attention row. grid(384), 256 threads.
// Per row i: Qk -> sim -> masked softmax -> T -> node_features
// ============================================================
__global__ __launch_bounds__(256) void k_attn(
    const float* __restrict__ edges,
    const float* __restrict__ Wk,
    const float* __restrict__ Wv)
{
    __shared__ float s_qi[256], s_Kni[256], s_Vni[256];
    __shared__ float s_Qk[64][8];    // transposed [e][h] for float4 broadcast
    __shared__ float s_p[384][12];   // transposed [j][h], stride 12 (16B-aligned)
    __shared__ float s_T[8][64];
    __shared__ float s_sb[8];
    __shared__ float s_mf[384];

    int i = blockIdx.x;
    int tid = threadIdx.x, lane = tid & 31, wid = tid >> 5;

    s_qi [tid] = g_q [tid * N + i];
    s_Kni[tid] = g_Kn[tid * N + i];
    s_Vni[tid] = g_Vn[tid * N + i];
    for (int j = tid; j < N; j += 256) s_mf[j] = g_mask[j];
    __syncthreads();

    const float rs = 0.17677669529663687f;  // 1/sqrt(32)

    // Qk[h][e] = rs * sum_a q[h*32+a] * Wk[h*32+a][128+e]
    #pragma unroll
    for (int rep = 0; rep < 2; rep++) {
        int h = (tid >> 6) + rep * 4;
        int e = tid & 63;
        const float* wkp = Wk + (h * 32) * 192 + 128 + e;
        float acc = 0.f;
        #pragma unroll
        for (int a = 0; a < 32; a++) acc = fmaf(s_qi[h * 32 + a], wkp[a * 192], acc);
        s_Qk[e][h] = acc * rs;
    }
    // sim_base[h] (warp h reduces q.Kn over its 32 channels)
    {
        float v = s_qi[tid] * s_Kni[tid];
        #pragma unroll
        for (int o = 16; o; o >>= 1) v += __shfl_xor_sync(0xffffffffu, v, o);
        if (lane == 0) s_sb[wid] = v * rs;
    }
    __syncthreads();

    const float* erow = edges + (size_t)i * N;

    // pass 1: sim[h][j] for all j
    for (int j = tid; j < N; j += 256) {
        float acc[8];
        #pragma unroll
        for (int h = 0; h < 8; h++) acc[h] = s_sb[h];
        #pragma unroll 8
        for (int e = 0; e < 64; e++) {
            float ev = __ldg(erow + (size_t)e * NN + j);
            float4 q0 = *(const float4*)&s_Qk[e][0];
            float4 q1 = *(const float4*)&s_Qk[e][4];
            acc[0] = fmaf(q0.x, ev, acc[0]); acc[1] = fmaf(q0.y, ev, acc[1]);
            acc[2] = fmaf(q0.z, ev, acc[2]); acc[3] = fmaf(q0.w, ev, acc[3]);
            acc[4] = fmaf(q1.x, ev, acc[4]); acc[5] = fmaf(q1.y, ev, acc[5]);
            acc[6] = fmaf(q1.z, ev, acc[6]); acc[7] = fmaf(q1.w, ev, acc[7]);
        }
        bool mj = s_mf[j] > 0.f;
        #pragma unroll
        for (int h = 0; h < 8; h++) s_p[j][h] = mj ? acc[h] : -INFINITY;
    }
    __syncthreads();

    float maski = s_mf[i];

    // masked softmax over j, warp `wid` owns head `wid`
    {
        int h = wid;
        float m = -INFINITY;
        for (int j = lane; j < N; j += 32) m = fmaxf(m, s_p[j][h]);
        #pragma unroll
        for (int o = 16; o; o >>= 1) m = fmaxf(m, __shfl_xor_sync(0xffffffffu, m, o));
        float sum = 0.f;
        for (int j = lane; j < N; j += 32) {
            float ev = __expf(s_p[j][h] - m);
            s_p[j][h] = ev;
            sum += ev;
        }
        #pragma unroll
        for (int o = 16; o; o >>= 1) sum += __shfl_xor_sync(0xffffffffu, sum, o);
        float inv = maski / sum;
        for (int j = lane; j < N; j += 32) s_p[j][h] *= inv;
    }
    __syncthreads();

    // pass 2: T[h][e] = sum_j p[h][j] * edges[e,i,j]; warp owns e = wid + 8k
    #pragma unroll 1
    for (int k = 0; k < 8; k++) {
        int e = wid + k * 8;
        const float* ep = erow + (size_t)e * NN;
        float acc[8];
        #pragma unroll
        for (int h = 0; h < 8; h++) acc[h] = 0.f;
        #pragma unroll 4
        for (int j = lane; j < N; j += 32) {
            float ev = __ldg(ep + j);
            float4 p0 = *(const float4*)&s_p[j][0];
            float4 p1 = *(const float4*)&s_p[j][4];
            acc[0] = fmaf(p0.x, ev, acc[0]); acc[1] = fmaf(p0.y, ev, acc[1]);
            acc[2] = fmaf(p0.z, ev, acc[2]); acc[3] = fmaf(p0.w, ev, acc[3]);
            acc[4] = fmaf(p1.x, ev, acc[4]); acc[5] = fmaf(p1.y, ev, acc[5]);
            acc[6] = fmaf(p1.z, ev, acc[6]); acc[7] = fmaf(p1.w, ev, acc[7]);
        }
        #pragma unroll
        for (int h = 0; h < 8; h++) {
            float a = acc[h];
            #pragma unroll
            for (int o = 16; o; o >>= 1) a += __shfl_xor_sync(0xffffffffu, a, o);
            if (lane == 0) s_T[h][e] = a;
        }
    }
    __syncthreads();

    // node_features[hv,i] = Vn*maski + sum_e Wv_edge[hv,e] * T[h][e]
    {
        int hv = tid, h = hv >> 5;
        const float* wvp = Wv + hv * 192 + 128;
        float acc = s_Vni[hv] * maski;
        #pragma unroll
        for (int e = 0; e < 64; e++) acc = fmaf(wvp[e], s_T[h][e], acc);
        g_nf[hv * N + i] = acc;
    }
}

// ============================================================
// Kernel 3: node_out = Wo@nf (128 rows) ; hEo = 0.5*We[:, :256]@nf (64 rows)
// M=192, K=256, Ncols=384. grid(3,3), 256 threads.
// ============================================================
__global__ __launch_bounds__(256) void k_post(
    const float* __restrict__ Wo,
    const float* __restrict__ We,
    float* __restrict__ out)
{
    __shared__ float Ws[64][33];
    __shared__ float Ns[32][132];
    int tid = threadIdx.x;
    int r0 = blockIdx.x * 64, n0 = blockIdx.y * 128;
    int og = tid >> 4, jg = tid & 15;
    int ro = og * 4, co = jg * 8;

    float acc[4][8];
    #pragma unroll
    for (int q = 0; q < 4; q++)
        #pragma unroll
        for (int u = 0; u < 8; u++) acc[q][u] = 0.f;

    for (int k0 = 0; k0 < 256; k0 += 32) {
        {
            int rr = tid >> 2, kk0 = (tid & 3) * 8;
            int r = r0 + rr;
            const float* wp = (r < 128) ? (Wo + r * 256) : (We + (r - 128) * 320);
            float4 a = *(const float4*)(wp + k0 + kk0);
            float4 b = *(const float4*)(wp + k0 + kk0 + 4);
            Ws[rr][kk0+0]=a.x; Ws[rr][kk0+1]=a.y; Ws[rr][kk0+2]=a.z; Ws[rr][kk0+3]=a.w;
            Ws[rr][kk0+4]=b.x; Ws[rr][kk0+5]=b.y; Ws[rr][kk0+6]=b.z; Ws[rr][kk0+7]=b.w;
        }
        {
            int kk = tid >> 3, nn0 = (tid & 7) * 16;
            const float* np = g_nf + (k0 + kk) * N + n0 + nn0;
            #pragma unroll
            for (int u = 0; u < 16; u += 4)
                *(float4*)&Ns[kk][nn0 + u] = *(const float4*)(np + u);
        }
        __syncthreads();
        #pragma unroll
        for (int kk = 0; kk < 32; kk++) {
            float w0 = Ws[ro+0][kk], w1 = Ws[ro+1][kk];
            float w2 = Ws[ro+2][kk], w3 = Ws[ro+3][kk];
            float4 nA = *(const float4*)&Ns[kk][co];
            float4 nB = *(const float4*)&Ns[kk][co+4];
            float nv[8] = {nA.x,nA.y,nA.z,nA.w,nB.x,nB.y,nB.z,nB.w};
            #pragma unroll
            for (int u = 0; u < 8; u++) {
                acc[0][u] = fmaf(w0, nv[u], acc[0][u]);
                acc[1][u] = fmaf(w1, nv[u], acc[1][u]);
                acc[2][u] = fmaf(w2, nv[u], acc[2][u]);
                acc[3][u] = fmaf(w3, nv[u], acc[3][u]);
            }
        }
        __syncthreads();
    }
    #pragma unroll
    for (int q = 0; q < 4; q++) {
        int r = r0 + ro + q;
        if (r < 128) {
            float* op = out + r * N + n0 + co;
            #pragma unroll
            for (int u = 0; u < 8; u++) op[u] = acc[q][u];
        } else {
            float* op = g_hEo + (r - 128) * N + n0 + co;
            #pragma unroll
            for (int u = 0; u < 8; u++) op[u] = 0.5f * acc[q][u];
        }
    }
}

// ============================================================
// Kernel 4: edge_out[o,i,j] = hEo[o,i] + hEo[o,j] + We_edge @ edges
// GEMM [64,64] x [64, 384*384]. grid(1152) = 384 i * 3 j-blocks of 128.
// ============================================================
__global__ __launch_bounds__(256) void k_edge(
    const float* __restrict__ edges,
    const float* __restrict__ We,
    float* __restrict__ out)
{
    __shared__ float Ws[64][64];    // [e][o] transposed weights
    __shared__ float Es[32][132];   // half-e staged edge tile

    int tid = threadIdx.x;
    int b = blockIdx.x;
    int i  = b / 3;
    int jb = (b % 3) * 128;

    // load We_edge transposed: Ws[e][o] = We[o*320 + 256 + e]
    {
        int o = tid >> 2, e0 = (tid & 3) * 16;
        const float* wp = We + o * 320 + 256 + e0;
        #pragma unroll
        for (int u = 0; u < 16; u += 4) {
            float4 w = *(const float4*)(wp + u);
            Ws[e0+u+0][o] = w.x; Ws[e0+u+1][o] = w.y;
            Ws[e0+u+2][o] = w.z; Ws[e0+u+3][o] = w.w;
        }
    }

    int og = tid >> 4, jg = tid & 15;
    int o0 = og * 4, j0 = jg * 8;
    float acc[4][8];
    #pragma unroll
    for (int q = 0; q < 4; q++)
        #pragma unroll
        for (int u = 0; u < 8; u++) acc[q][u] = 0.f;

    for (int s = 0; s < 2; s++) {
        __syncthreads();
        {
            int er = tid >> 3, jj0 = (tid & 7) * 16;
            const float* ep = edges + (size_t)(s * 32 + er) * NN + (size_t)i * N + jb + jj0;
            #pragma unroll
            for (int u = 0; u < 16; u += 4)
                *(float4*)&Es[er][jj0 + u] = *(const float4*)(ep + u);
        }
        __syncthreads();
        #pragma unroll
        for (int e = 0; e < 32; e++) {
            float4 w  = *(const float4*)&Ws[s * 32 + e][o0];
            float4 eA = *(const float4*)&Es[e][j0];
            float4 eB = *(const float4*)&Es[e][j0 + 4];
            float ev[8] = {eA.x,eA.y,eA.z,eA.w,eB.x,eB.y,eB.z,eB.w};
            #pragma unroll
            for (int u = 0; u < 8; u++) {
                acc[0][u] = fmaf(w.x, ev[u], acc[0][u]);
                acc[1][u] = fmaf(w.y, ev[u], acc[1][u]);
                acc[2][u] = fmaf(w.z, ev[u], acc[2][u]);
                acc[3][u] = fmaf(w.w, ev[u], acc[3][u]);
            }
        }
    }

    float* ob = out + 128 * N;   // edge_out starts after node_out
    #pragma unroll
    for (int q = 0; q < 4; q++) {
        int o = o0 + q;
        float eoi = g_hEo[o * N + i];
        const float* eoj = g_hEo + o * N + jb + j0;
        float* op = ob + (size_t)o * NN + (size_t)i * N + jb + j0;
        #pragma unroll
        for (int u = 0; u < 8; u++) op[u] = acc[q][u] + eoi + eoj[u];
    }
}

// ============================================================
extern "C" void kernel_launch(void* const* d_in, const int* in_sizes, int n_in,
                              void* d_out, int out_size)
{
    const float* nodes = (const float*)d_in[0];
    const float* edges = (const float*)d_in[1];
    const unsigned int* mask = (const unsigned int*)d_in[2];
    const float* Wq = (const float*)d_in[3];
    const float* Wk = (const float*)d_in[4];
    const float* Wv = (const float*)d_in[5];
    const float* Wo = (const float*)d_in[6];
    const float* We = (const float*)d_in[7];
    float* out = (float*)d_out;

    k_mask<<<1, 384>>>(mask);
    k_prep<<<dim3(12, 3), 256>>>(nodes, Wq, Wk, Wv);
    k_attn<<<384, 256>>>(edges, Wk, Wv);
    k_post<<<dim3(3, 3), 256>>>(Wo, We, out);
    k_edge<<<1152, 256>>>(edges, We, out);
}

// round 3
// speedup vs baseline: 1.4479x; 1.4479x over previous
#include <cuda_runtime.h>
#include <math.h>

#define N   384
#define NN  (384*384)

// ---- scratch (device globals; no allocation allowed) ----
__device__ float g_q   [256*N];
__device__ float g_Kn  [256*N];
__device__ float g_Vn  [256*N];
__device__ float g_nf  [256*N];
__device__ float g_hEo [64*N];
__device__ float g_mask[N];

// ---- packed f32x2 helpers (Blackwell FFMA2) ----
__device__ __forceinline__ unsigned long long pk2(float a, float b) {
    unsigned long long d;
    asm("mov.b64 %0, {%1, %2};" : "=l"(d) : "f"(a), "f"(b));
    return d;
}
__device__ __forceinline__ unsigned long long fma2(unsigned long long a,
                                                   unsigned long long b,
                                                   unsigned long long c) {
    unsigned long long d;
    asm("fma.rn.f32x2 %0, %1, %2, %3;" : "=l"(d) : "l"(a), "l"(b), "l"(c));
    return d;
}
__device__ __forceinline__ float2 upk(unsigned long long v) {
    float2 r;
    asm("mov.b64 {%0, %1}, %2;" : "=f"(r.x), "=f"(r.y) : "l"(v));
    return r;
}
union F4U { float4 f; unsigned long long u[2]; };

// ============================================================
// Kernel 1: fused GEMM q|Kn|Vn. M=768, K=128, cols=384.
// grid(24,12), 256 thr, tile 32x32. Block(0,0) also decodes mask.
// ============================================================
__global__ __launch_bounds__(256) void k_prep(
    const float* __restrict__ nodes,
    const float* __restrict__ Wq,
    const float* __restrict__ Wk,
    const float* __restrict__ Wv,
    const unsigned int* __restrict__ maskw)
{
    __shared__ float Ws[32][33];
    __shared__ float Ns[32][36];
    __shared__ int s_mode;
    int tid = threadIdx.x;

    if (blockIdx.x == 0 && blockIdx.y == 0) {
        if (tid == 0) {
            int md = 0;
            for (int w = 0; w < 96; w++) {
                unsigned v = maskw[w];
                if (v == 0x3f800000u) { md = 0; break; }   // float32
                if (v > 1u)           { md = 2; break; }   // packed u8
            }
            s_mode = md;
        }
        __syncthreads();
        int mode = s_mode;
        for (int j = tid; j < N; j += 256) {
            float val;
            if (mode == 2) {
                unsigned w = maskw[j >> 2];
                val = ((w >> ((j & 3) * 8)) & 0xffu) ? 1.0f : 0.0f;
            } else {
                val = maskw[j] ? 1.0f : 0.0f;   // int32 or f32 bits
            }
            g_mask[j] = val;
        }
    }

    int r0 = blockIdx.x * 32, n0 = blockIdx.y * 32;
    int co = tid & 31, ro = (tid >> 5) * 4;
    float acc[4] = {0.f, 0.f, 0.f, 0.f};

    for (int k0 = 0; k0 < 128; k0 += 32) {
        {
            int rr = tid >> 3, kl = (tid & 7) * 4;
            int r = r0 + rr;
            const float* wp;
            if      (r < 256) wp = Wq + r * 128;
            else if (r < 512) wp = Wk + (r - 256) * 192;
            else              wp = Wv + (r - 512) * 192;
            float4 w = *(const float4*)(wp + k0 + kl);
            Ws[rr][kl+0] = w.x; Ws[rr][kl+1] = w.y;
            Ws[rr][kl+2] = w.z; Ws[rr][kl+3] = w.w;
        }
        {
            int kk = tid >> 3, cl = (tid & 7) * 4;
            float4 v = *(const float4*)(nodes + (k0 + kk) * N + n0 + cl);
            Ns[kk][cl+0] = v.x; Ns[kk][cl+1] = v.y;
            Ns[kk][cl+2] = v.z; Ns[kk][cl+3] = v.w;
        }
        __syncthreads();
        #pragma unroll
        for (int k = 0; k < 32; k++) {
            float ev = Ns[k][co];
            acc[0] = fmaf(Ws[ro+0][k], ev, acc[0]);
            acc[1] = fmaf(Ws[ro+1][k], ev, acc[1]);
            acc[2] = fmaf(Ws[ro+2][k], ev, acc[2]);
            acc[3] = fmaf(Ws[ro+3][k], ev, acc[3]);
        }
        __syncthreads();
    }
    #pragma unroll
    for (int q = 0; q < 4; q++) {
        int r = r0 + ro + q;
        float* op;
        if      (r < 256) op = g_q  + r * N;
        else if (r < 512) op = g_Kn + (r - 256) * N;
        else              op = g_Vn + (r - 512) * N;
        op[n0 + co] = acc[q];
    }
}

// ============================================================
// Kernel 2: fused attention row, single pass over edges.
// grid(384), 256 thr, ~126KB dynamic smem (1 CTA/SM).
// ============================================================
#define ES_STRIDE 388
#define ATTN_SMEM ((64*ES_STRIDE + 384*12 + 3*256 + 512 + 512 + 8 + 384) * 4)

__global__ __launch_bounds__(256) void k_attn(
    const float* __restrict__ edges,
    const float* __restrict__ Wk,
    const float* __restrict__ Wv)
{
    extern __shared__ float sm[];
    float* Es    = sm;                     // [64][388]
    float* s_p   = Es + 64 * ES_STRIDE;    // [384][12]
    float* s_qi  = s_p + 384 * 12;         // 256
    float* s_Kni = s_qi + 256;
    float* s_Vni = s_Kni + 256;
    float* s_Qk  = s_Vni + 256;            // [64][8]
    float* s_T   = s_Qk + 512;             // [8][64]
    float* s_sb  = s_T + 512;              // 8
    float* s_mf  = s_sb + 8;               // 384

    int i = blockIdx.x;
    int tid = threadIdx.x, lane = tid & 31, wid = tid >> 5;

    s_qi [tid] = g_q [tid * N + i];
    s_Kni[tid] = g_Kn[tid * N + i];
    s_Vni[tid] = g_Vn[tid * N + i];
    for (int j = tid; j < N; j += 256) s_mf[j] = g_mask[j];

    // stage edges[0..63, i, 0..383] into smem (coalesced float4)
    const float* erow = edges + (size_t)i * N;
    for (int idx = tid; idx < 64 * 96; idx += 256) {
        int e = idx / 96, j4 = idx - e * 96;
        float4 v = *(const float4*)(erow + (size_t)e * NN + j4 * 4);
        *(float4*)&Es[e * ES_STRIDE + j4 * 4] = v;
    }
    __syncthreads();

    const float rs = 0.17677669529663687f;  // 1/sqrt(32)

    // Qk[e][h] = rs * sum_a q[h*32+a] * Wk[h*32+a][128+e]
    #pragma unroll
    for (int rep = 0; rep < 2; rep++) {
        int h = (tid >> 6) + rep * 4;
        int e = tid & 63;
        const float* wkp = Wk + (h * 32) * 192 + 128 + e;
        float acc = 0.f;
        #pragma unroll
        for (int a = 0; a < 32; a++) acc = fmaf(s_qi[h * 32 + a], wkp[a * 192], acc);
        s_Qk[e * 8 + h] = acc * rs;
    }
    {   // sim_base[h]
        float v = s_qi[tid] * s_Kni[tid];
        #pragma unroll
        for (int o = 16; o; o >>= 1) v += __shfl_xor_sync(0xffffffffu, v, o);
        if (lane == 0) s_sb[wid] = v * rs;
    }
    __syncthreads();

    // pass 1: sim[h][j] (packed along h-pairs)
    F4U sb0; sb0.f = *(const float4*)&s_sb[0];
    F4U sb1; sb1.f = *(const float4*)&s_sb[4];
    for (int j = tid; j < N; j += 256) {
        unsigned long long acc2[4] = { sb0.u[0], sb0.u[1], sb1.u[0], sb1.u[1] };
        #pragma unroll 8
        for (int e = 0; e < 64; e++) {
            float ev = Es[e * ES_STRIDE + j];
            unsigned long long evd = pk2(ev, ev);
            F4U q0; q0.f = *(const float4*)&s_Qk[e * 8];
            F4U q1; q1.f = *(const float4*)&s_Qk[e * 8 + 4];
            acc2[0] = fma2(q0.u[0], evd, acc2[0]);
            acc2[1] = fma2(q0.u[1], evd, acc2[1]);
            acc2[2] = fma2(q1.u[0], evd, acc2[2]);
            acc2[3] = fma2(q1.u[1], evd, acc2[3]);
        }
        bool mj = s_mf[j] > 0.f;
        if (mj) {
            F4U o0, o1;
            float2 a = upk(acc2[0]), b = upk(acc2[1]);
            float2 c = upk(acc2[2]), d = upk(acc2[3]);
            o0.f = make_float4(a.x, a.y, b.x, b.y);
            o1.f = make_float4(c.x, c.y, d.x, d.y);
            *(float4*)&s_p[j * 12]     = o0.f;
            *(float4*)&s_p[j * 12 + 4] = o1.f;
        } else {
            float4 ninf = make_float4(-INFINITY, -INFINITY, -INFINITY, -INFINITY);
            *(float4*)&s_p[j * 12]     = ninf;
            *(float4*)&s_p[j * 12 + 4] = ninf;
        }
    }
    __syncthreads();

    float maski = s_mf[i];

    // masked softmax: warp h owns head h
    {
        int h = wid;
        float m = -INFINITY;
        for (int j = lane; j < N; j += 32) m = fmaxf(m, s_p[j * 12 + h]);
        #pragma unroll
        for (int o = 16; o; o >>= 1) m = fmaxf(m, __shfl_xor_sync(0xffffffffu, m, o));
        float sum = 0.f;
        for (int j = lane; j < N; j += 32) {
            float ev = __expf(s_p[j * 12 + h] - m);
            s_p[j * 12 + h] = ev;
            sum += ev;
        }
        #pragma unroll
        for (int o = 16; o; o >>= 1) sum += __shfl_xor_sync(0xffffffffu, sum, o);
        float inv = maski / sum;
        for (int j = lane; j < N; j += 32) s_p[j * 12 + h] *= inv;
    }
    __syncthreads();

    // pass 2: T[h][e] = sum_j p[h][j] * E[e][j] from smem (packed h-pairs)
    #pragma unroll 1
    for (int k = 0; k < 8; k++) {
        int e = wid + k * 8;
        const float* ep = Es + e * ES_STRIDE;
        unsigned long long acc2[4] = {0ull, 0ull, 0ull, 0ull};
        #pragma unroll 4
        for (int j = lane; j < N; j += 32) {
            float ev = ep[j];
            unsigned long long evd = pk2(ev, ev);
            F4U p0; p0.f = *(const float4*)&s_p[j * 12];
            F4U p1; p1.f = *(const float4*)&s_p[j * 12 + 4];
            acc2[0] = fma2(p0.u[0], evd, acc2[0]);
            acc2[1] = fma2(p0.u[1], evd, acc2[1]);
            acc2[2] = fma2(p1.u[0], evd, acc2[2]);
            acc2[3] = fma2(p1.u[1], evd, acc2[3]);
        }
        #pragma unroll
        for (int hp = 0; hp < 4; hp++) {
            float2 v = upk(acc2[hp]);
            #pragma unroll
            for (int o = 16; o; o >>= 1) {
                v.x += __shfl_xor_sync(0xffffffffu, v.x, o);
                v.y += __shfl_xor_sync(0xffffffffu, v.y, o);
            }
            if (lane == 0) {
                s_T[(2 * hp)     * 64 + e] = v.x;
                s_T[(2 * hp + 1) * 64 + e] = v.y;
            }
        }
    }
    __syncthreads();

    // node_features[hv,i]
    {
        int hv = tid, h = hv >> 5;
        const float* wvp = Wv + hv * 192 + 128;
        float acc = s_Vni[hv] * maski;
        #pragma unroll
        for (int e = 0; e < 64; e++) acc = fmaf(wvp[e], s_T[h * 64 + e], acc);
        g_nf[hv * N + i] = acc;
    }
}

// ============================================================
// Kernel 3: node_out = Wo@nf ; hEo = 0.5*We[:,:256]@nf
// M=192, K=256, cols=384. grid(6,12), 256 thr, tile 32x32.
// ============================================================
__global__ __launch_bounds__(256) void k_post(
    const float* __restrict__ Wo,
    const float* __restrict__ We,
    float* __restrict__ out)
{
    __shared__ float Ws[32][33];
    __shared__ float Ns[32][36];
    int tid = threadIdx.x;
    int r0 = blockIdx.x * 32, n0 = blockIdx.y * 32;
    int co = tid & 31, ro = (tid >> 5) * 4;
    float acc[4] = {0.f, 0.f, 0.f, 0.f};

    for (int k0 = 0; k0 < 256; k0 += 32) {
        {
            int rr = tid >> 3, kl = (tid & 7) * 4;
            int r = r0 + rr;
            const float* wp = (r < 128) ? (Wo + r * 256) : (We + (r - 128) * 320);
            float4 w = *(const float4*)(wp + k0 + kl);
            Ws[rr][kl+0] = w.x; Ws[rr][kl+1] = w.y;
            Ws[rr][kl+2] = w.z; Ws[rr][kl+3] = w.w;
        }
        {
            int kk = tid >> 3, cl = (tid & 7) * 4;
            float4 v = *(const float4*)(g_nf + (k0 + kk) * N + n0 + cl);
            Ns[kk][cl+0] = v.x; Ns[kk][cl+1] = v.y;
            Ns[kk][cl+2] = v.z; Ns[kk][cl+3] = v.w;
        }
        __syncthreads();
        #pragma unroll
        for (int k = 0; k < 32; k++) {
            float ev = Ns[k][co];
            acc[0] = fmaf(Ws[ro+0][k], ev, acc[0]);
            acc[1] = fmaf(Ws[ro+1][k], ev, acc[1]);
            acc[2] = fmaf(Ws[ro+2][k], ev, acc[2]);
            acc[3] = fmaf(Ws[ro+3][k], ev, acc[3]);
        }
        __syncthreads();
    }
    #pragma unroll
    for (int q = 0; q < 4; q++) {
        int r = r0 + ro + q;
        if (r < 128) out[r * N + n0 + co] = acc[q];
        else         g_hEo[(r - 128) * N + n0 + co] = 0.5f * acc[q];
    }
}

// ============================================================
// Kernel 4: edge_out[o,i,j] = hEo[o,i]+hEo[o,j] + We_edge@edges
// grid(768) = 384 i x 2 j-halves of 192. block 192.
// Thread tile: 8 o x 8 j, FFMA2 packed along o-pairs.
// ============================================================
__global__ __launch_bounds__(192) void k_edge(
    const float* __restrict__ edges,
    const float* __restrict__ We,
    float* __restrict__ out)
{
    __shared__ float Ws[64][68];    // [e][o]
    __shared__ float Es[32][196];

    int tid = threadIdx.x;
    int b = blockIdx.x;
    int i  = b >> 1;
    int jb = (b & 1) * 192;

    // load We_edge transposed: Ws[e][o]
    if (tid < 128) {
        int o = tid >> 1, e0 = (tid & 1) * 32;
        const float* wp = We + o * 320 + 256 + e0;
        #pragma unroll
        for (int u = 0; u < 32; u += 4) {
            float4 w = *(const float4*)(wp + u);
            Ws[e0+u+0][o] = w.x; Ws[e0+u+1][o] = w.y;
            Ws[e0+u+2][o] = w.z; Ws[e0+u+3][o] = w.w;
        }
    }

    int og = tid / 24, jg = tid % 24;
    int o0 = og * 8, j0 = jg * 8;

    unsigned long long acc2[4][8];
    #pragma unroll
    for (int op = 0; op < 4; op++)
        #pragma unroll
        for (int j = 0; j < 8; j++) acc2[op][j] = 0ull;

    for (int s = 0; s < 2; s++) {
        __syncthreads();
        {   // stage 32 e-rows x 192 j
            #pragma unroll
            for (int it = 0; it < 8; it++) {
                int idx = it * 192 + tid;
                int e = idx / 48, j4 = idx % 48;
                float4 v = *(const float4*)(edges + (size_t)(s * 32 + e) * NN
                                            + (size_t)i * N + jb + j4 * 4);
                *(float4*)&Es[e][j4 * 4] = v;
            }
        }
        __syncthreads();
        #pragma unroll 4
        for (int e = 0; e < 32; e++) {
            int eg = s * 32 + e;
            F4U w0; w0.f = *(const float4*)&Ws[eg][o0];
            F4U w1; w1.f = *(const float4*)&Ws[eg][o0 + 4];
            F4U a;  a.f  = *(const float4*)&Es[e][j0];
            F4U c;  c.f  = *(const float4*)&Es[e][j0 + 4];
            float ev[8] = {a.f.x, a.f.y, a.f.z, a.f.w, c.f.x, c.f.y, c.f.z, c.f.w};
            unsigned long long wp[4] = {w0.u[0], w0.u[1], w1.u[0], w1.u[1]};
            #pragma unroll
            for (int j = 0; j < 8; j++) {
                unsigned long long evd = pk2(ev[j], ev[j]);
                acc2[0][j] = fma2(wp[0], evd, acc2[0][j]);
                acc2[1][j] = fma2(wp[1], evd, acc2[1][j]);
                acc2[2][j] = fma2(wp[2], evd, acc2[2][j]);
                acc2[3][j] = fma2(wp[3], evd, acc2[3][j]);
            }
        }
    }

    float* ob = out + 128 * N;   // edge_out after node_out
    #pragma unroll
    for (int op = 0; op < 4; op++) {
        int oA = o0 + 2 * op, oB = oA + 1;
        float eoiA = g_hEo[oA * N + i];
        float eoiB = g_hEo[oB * N + i];
        float4 ejA0 = *(const float4*)(g_hEo + oA * N + jb + j0);
        float4 ejA1 = *(const float4*)(g_hEo + oA * N + jb + j0 + 4);
        float4 ejB0 = *(const float4*)(g_hEo + oB * N + jb + j0);
        float4 ejB1 = *(const float4*)(g_hEo + oB * N + jb + j0 + 4);
        float ejA[8] = {ejA0.x, ejA0.y, ejA0.z, ejA0.w, ejA1.x, ejA1.y, ejA1.z, ejA1.w};
        float ejB[8] = {ejB0.x, ejB0.y, ejB0.z, ejB0.w, ejB1.x, ejB1.y, ejB1.z, ejB1.w};
        float rA[8], rB[8];
        #pragma unroll
        for (int j = 0; j < 8; j++) {
            float2 v = upk(acc2[op][j]);
            rA[j] = v.x + eoiA + ejA[j];
            rB[j] = v.y + eoiB + ejB[j];
        }
        float* pA = ob + (size_t)oA * NN + (size_t)i * N + jb + j0;
        float* pB = ob + (size_t)oB * NN + (size_t)i * N + jb + j0;
        *(float4*)pA       = make_float4(rA[0], rA[1], rA[2], rA[3]);
        *(float4*)(pA + 4) = make_float4(rA[4], rA[5], rA[6], rA[7]);
        *(float4*)pB       = make_float4(rB[0], rB[1], rB[2], rB[3]);
        *(float4*)(pB + 4) = make_float4(rB[4], rB[5], rB[6], rB[7]);
    }
}

// ============================================================
extern "C" void kernel_launch(void* const* d_in, const int* in_sizes, int n_in,
                              void* d_out, int out_size)
{
    const float* nodes = (const float*)d_in[0];
    const float* edges = (const float*)d_in[1];
    const unsigned int* mask = (const unsigned int*)d_in[2];
    const float* Wq = (const float*)d_in[3];
    const float* Wk = (const float*)d_in[4];
    const float* Wv = (const float*)d_in[5];
    const float* Wo = (const float*)d_in[6];
    const float* We = (const float*)d_in[7];
    float* out = (float*)d_out;

    cudaFuncSetAttribute(k_attn, cudaFuncAttributeMaxDynamicSharedMemorySize, ATTN_SMEM);

    k_prep<<<dim3(24, 12), 256>>>(nodes, Wq, Wk, Wv, mask);
    k_attn<<<384, 256, ATTN_SMEM>>>(edges, Wk, Wv);
    k_post<<<dim3(6, 12), 256>>>(Wo, We, out);
    k_edge<<<768, 192>>>(edges, We, out);
}